// round 12
// baseline (speedup 1.0000x reference)
#include <cuda_runtime.h>
#include <cuda_bf16.h>
#include <cuda_fp16.h>
#include <cstdint>

#define H 128
#define NBUCKETS 9
#define THREADS_E 512
#define THREADS_M 256
#define G_TILES 8

#define RSTRIDE_E 136   // elems; 272B rows, 17*16B -> ldmatrix conflict-free
#define RSTRIDE_B 272

// ---------------- device scratch ----------------
__device__ float4 g_accum4[100000 * (H / 4)];
__device__ int    g_perm[1000000];
__device__ int    g_hist[16];
__device__ int    g_start[NBUCKETS];
__device__ int    g_count[NBUCKETS];
__device__ int    g_cursor[NBUCKETS];
__device__ int    g_groupOff[NBUCKETS + 1];
// slots 0..7 experts (fp16, B^T[n][k]=W[k][n]); 8..11 = MLP w1,w2,w3,wout (fp16 hi/lo)
__device__ __align__(16) unsigned short g_wsp_hi[12][128][RSTRIDE_E];
__device__ __align__(16) unsigned short g_wsp_lo[12][128][RSTRIDE_E];

// ---------------- helpers ----------------
__device__ __forceinline__ int bucket_of(float d) {
    float t = (d - 0.8f) / 5.0001f * 8.0f;
    float f = floorf(t);
    return (f >= 0.0f && f < 8.0f) ? (int)f : 8;
}

__device__ __forceinline__ void red_add_v4(float* p, float a, float b, float c, float d) {
    asm volatile("red.global.add.v4.f32 [%0], {%1,%2,%3,%4};"
                 :: "l"(p), "f"(a), "f"(b), "f"(c), "f"(d) : "memory");
}

__device__ __forceinline__ uint32_t smem_u32(const void* p) {
    uint32_t a;
    asm("{ .reg .u64 t; cvta.to.shared.u64 t, %1; cvt.u32.u64 %0, t; }" : "=r"(a) : "l"(p));
    return a;
}

#define CP16(dst, src) asm volatile("cp.async.cg.shared.global [%0], [%1], 16;" :: "r"(dst), "l"(src))
#define CP8(dst, src)  asm volatile("cp.async.ca.shared.global [%0], [%1], 8;"  :: "r"(dst), "l"(src))
#define CP_COMMIT()    asm volatile("cp.async.commit_group;" ::: "memory")
#define CP_WAIT0()     asm volatile("cp.async.wait_group 0;" ::: "memory")

__device__ __forceinline__ void ldsm_x4(uint32_t& r0, uint32_t& r1, uint32_t& r2, uint32_t& r3,
                                        uint32_t addr) {
    asm volatile("ldmatrix.sync.aligned.m8n8.x4.shared.b16 {%0,%1,%2,%3}, [%4];"
                 : "=r"(r0), "=r"(r1), "=r"(r2), "=r"(r3) : "r"(addr));
}

__device__ __forceinline__ void mma_fp16(float* d, uint32_t a0, uint32_t a1, uint32_t a2,
                                         uint32_t a3, uint32_t b0, uint32_t b1) {
    asm volatile("mma.sync.aligned.m16n8k16.row.col.f32.f16.f16.f32 "
                 "{%0,%1,%2,%3}, {%4,%5,%6,%7}, {%8,%9}, {%0,%1,%2,%3};"
                 : "+f"(d[0]), "+f"(d[1]), "+f"(d[2]), "+f"(d[3])
                 : "r"(a0), "r"(a1), "r"(a2), "r"(a3), "r"(b0), "r"(b1));
}

__device__ __forceinline__ uint32_t pack_half2(float v0, float v1) {
    __half h0 = __float2half_rn(v0), h1 = __float2half_rn(v1);
    return (uint32_t)__half_as_ushort(h0) | ((uint32_t)__half_as_ushort(h1) << 16);
}

// fp16 pass for k_mlp: acc[16][4] += A(16x128 stripe at m0) * B^T(128x128)
__device__ __forceinline__ void mma_stripe_fp(float (*acc)[4], uint32_t aBase, uint32_t bBase,
                                              int lane, int m0) {
    uint32_t aAddr = aBase + (uint32_t)(m0 + (lane & 15)) * RSTRIDE_B
                   + (uint32_t)((lane >> 4) << 4);
    uint32_t bAddr = bBase + (uint32_t)((lane & 7) + ((lane >> 4) << 3)) * RSTRIDE_B
                   + (uint32_t)(((lane >> 3) & 1) << 4);
    #pragma unroll
    for (int k0 = 0; k0 < 8; k0++) {
        uint32_t a0, a1, a2, a3;
        ldsm_x4(a0, a1, a2, a3, aAddr + k0 * 32);
        #pragma unroll
        for (int j2 = 0; j2 < 8; j2++) {
            uint32_t b0, b1, b2, b3;
            ldsm_x4(b0, b1, b2, b3, bAddr + j2 * (16 * RSTRIDE_B) + k0 * 32);
            mma_fp16(acc[j2 * 2],     a0, a1, a2, a3, b0, b1);
            mma_fp16(acc[j2 * 2 + 1], a0, a1, a2, a3, b2, b3);
        }
    }
}

// 32x32 warp tile, fp16: acc[2][4][4] += A(32 rows at m0) * B^T(32 cols at n0)
__device__ __forceinline__ void mma_pass32_fp(float (*acc)[4][4], uint32_t aBase, uint32_t bBase,
                                              int lane, int m0, int n0) {
    uint32_t aAddr = aBase + (uint32_t)(m0 + (lane & 15)) * RSTRIDE_B
                   + (uint32_t)((lane >> 4) << 4);
    uint32_t bAddr = bBase + (uint32_t)(n0 + (lane & 7) + ((lane >> 4) << 3)) * RSTRIDE_B
                   + (uint32_t)(((lane >> 3) & 1) << 4);
    #pragma unroll
    for (int k0 = 0; k0 < 8; k0++) {
        uint32_t a0, a1, a2, a3, c0, c1, c2, c3;
        ldsm_x4(a0, a1, a2, a3, aAddr + k0 * 32);
        ldsm_x4(c0, c1, c2, c3, aAddr + 16 * RSTRIDE_B + k0 * 32);
        #pragma unroll
        for (int j2 = 0; j2 < 2; j2++) {
            uint32_t b0, b1, b2, b3;
            ldsm_x4(b0, b1, b2, b3, bAddr + j2 * (16 * RSTRIDE_B) + k0 * 32);
            mma_fp16(acc[0][j2 * 2],     a0, a1, a2, a3, b0, b1);
            mma_fp16(acc[0][j2 * 2 + 1], a0, a1, a2, a3, b2, b3);
            mma_fp16(acc[1][j2 * 2],     c0, c1, c2, c3, b0, b1);
            mma_fp16(acc[1][j2 * 2 + 1], c0, c1, c2, c3, b2, b3);
        }
    }
}

// ---------------- small kernels ----------------
__global__ void k_zero(int n4) {
    int i = blockIdx.x * blockDim.x + threadIdx.x;
    int stride = gridDim.x * blockDim.x;
    float4 z = make_float4(0.f, 0.f, 0.f, 0.f);
    for (; i < n4; i += stride) g_accum4[i] = z;
    if (blockIdx.x == 0 && threadIdx.x < 16) g_hist[threadIdx.x] = 0;
}

__global__ void k_hist(const float* __restrict__ dist, int E) {
    __shared__ int lh[NBUCKETS];
    if (threadIdx.x < NBUCKETS) lh[threadIdx.x] = 0;
    __syncthreads();
    int i = blockIdx.x * blockDim.x + threadIdx.x;
    int stride = gridDim.x * blockDim.x;
    for (; i < E; i += stride) atomicAdd(&lh[bucket_of(dist[i])], 1);
    __syncthreads();
    if (threadIdx.x < NBUCKETS) atomicAdd(&g_hist[threadIdx.x], lh[threadIdx.x]);
}

__global__ void k_scan() {
    if (threadIdx.x == 0 && blockIdx.x == 0) {
        int off = 0, goff = 0;
        for (int s = 0; s < NBUCKETS; s++) {
            int c = g_hist[s];
            g_start[s] = off; g_cursor[s] = off; g_count[s] = c;
            g_groupOff[s] = goff;
            off += c;
            goff += (c + G_TILES * 128 - 1) / (G_TILES * 128);
        }
        g_groupOff[NBUCKETS] = goff;
    }
}

__global__ void k_scatter(const float* __restrict__ dist, int E) {
    int lane = threadIdx.x & 31;
    unsigned ltmask = (1u << lane) - 1u;
    int i = blockIdx.x * blockDim.x + threadIdx.x;
    int stride = gridDim.x * blockDim.x;
    for (; i < E; i += stride) {
        int s = bucket_of(dist[i]);
        unsigned m = __match_any_sync(0xffffffffu, s);
        int leader = __ffs(m) - 1;
        int base = 0;
        if (lane == leader) base = atomicAdd(&g_cursor[s], __popc(m));
        base = __shfl_sync(0xffffffffu, base, leader);
        g_perm[base + __popc(m & ltmask)] = i;
    }
}

__global__ void k_wprep(const float* __restrict__ sel_w, const float* __restrict__ w1,
                        const float* __restrict__ w2, const float* __restrict__ w3,
                        const float* __restrict__ wout) {
    int slot = blockIdx.x;
    const float* src;
    bool tr;
    if (slot < 8) { src = sel_w + (size_t)slot * (H * H); tr = true; }
    else {
        const float* m[4] = {w1, w2, w3, wout};
        src = m[slot - 8]; tr = false;
    }
    for (int idx = threadIdx.x; idx < H * H; idx += blockDim.x) {
        int n = idx >> 7, k = idx & 127;
        float w = tr ? src[k * H + n] : src[n * H + k];
        if (slot < 8) {
            g_wsp_hi[slot][n][k] = __half_as_ushort(__float2half_rn(w));
        } else {   // fp16 split-2 for MLP (2-pass)
            __half hh = __float2half_rn(w);
            __half ll = __float2half_rn(w - __half2float(hh));
            g_wsp_hi[slot][n][k] = __half_as_ushort(hh);
            g_wsp_lo[slot][n][k] = __half_as_ushort(ll);
        }
    }
}

// ---------------- kernel: edge expert GEMM (shuffle-combined v4 scatter) ----------------
#define SM_META 0
#define SM_WT   32
#define SM_PERM (SM_WT + 3072)
#define SM_NODE (SM_PERM + 4096)
#define SM_RBF  (SM_NODE + 4096)
#define SM_XBUF (SM_RBF + 3072 + 32)
#define SM_AHI  (SM_XBUF + 65536)
#define SM_BHI  (SM_AHI + 34816)
#define EDGE_SMEM_BYTES (SM_BHI + 34816)

__device__ __forceinline__ void issue_tile(const float* x, const float* rbf,
                                           const int* pt, uint32_t sbase, int t) {
    #pragma unroll 4
    for (int idx = t; idx < 4096; idx += THREADS_E) {
        int r = idx >> 5, seg = idx & 31;
        const char* src = (const char*)(x + (size_t)pt[r] * H) + seg * 16;
        CP16(sbase + SM_XBUF + r * 512 + seg * 16, src);
    }
    if (t < 384) {
        int r = t / 3, p = t - r * 3;
        const char* src = (const char*)(rbf + (size_t)pt[r] * 6) + p * 8;
        CP8(sbase + SM_RBF + r * 24 + p * 8, src);
    }
}

__global__ void __launch_bounds__(THREADS_E, 1)
k_edge(const float* __restrict__ x, const float* __restrict__ rbf,
       const int* __restrict__ eidx, const float* __restrict__ w_rbf)
{
    extern __shared__ char sm[];
    int*   meta  = (int*)(sm + SM_META);
    float* sWT   = (float*)(sm + SM_WT);
    int*   permG = (int*)(sm + SM_PERM);
    int*   nodeG = (int*)(sm + SM_NODE);
    float* sRbf  = (float*)(sm + SM_RBF);
    uint32_t sbase = smem_u32(sm);

    int t = threadIdx.x, wid = t >> 5, lane = t & 31;

    if (t == 0) {
        int b = blockIdx.x;
        int found = -1, grpLocal = 0;
        if (b < g_groupOff[NBUCKETS]) {
            #pragma unroll
            for (int q = 0; q < NBUCKETS; q++)
                if (b >= g_groupOff[q] && b < g_groupOff[q + 1]) { found = q; grpLocal = b - g_groupOff[q]; }
        }
        if (found < 0) meta[0] = -1;
        else {
            int rowBase = grpLocal * (G_TILES * 128);
            int rem = g_count[found] - rowBase;
            if (rem > G_TILES * 128) rem = G_TILES * 128;
            meta[0] = found;
            meta[1] = (rem + 127) >> 7;
            meta[2] = g_start[found] + rowBase;
            meta[3] = rem;
        }
    }
    __syncthreads();
    int s = meta[0];
    if (s < 0) return;
    int nTiles = meta[1], rowStart = meta[2], rem = meta[3];

    for (int idx = t; idx < nTiles * 128; idx += THREADS_E)
        permG[idx] = (idx < rem) ? g_perm[rowStart + idx] : g_perm[rowStart];
    for (int idx = t; idx < 768; idx += THREADS_E) {
        int q = idx >> 7, c = idx & 127;
        sWT[idx] = w_rbf[c * 6 + q];
    }
    __syncthreads();
    for (int idx = t; idx < nTiles * 128; idx += THREADS_E)
        nodeG[idx] = eidx[permG[idx]];

    if (s < 8) {   // expert weight (fp16), once per group
        const char* srcH = (const char*)&g_wsp_hi[s][0][0];
        for (int i = t * 16; i < 34816; i += THREADS_E * 16)
            CP16(sbase + SM_BHI + i, srcH + i);
    }
    issue_tile(x, rbf, permG, sbase, t);
    CP_COMMIT();
    CP_WAIT0();
    __syncthreads();

    int c0 = lane * 4;
    float4 wq[6];
    #pragma unroll
    for (int q = 0; q < 6; q++) wq[q] = *(float4*)&sWT[q * 128 + c0];

    int mi = wid & 3, nj = wid >> 2;
    int m0 = mi * 32, n0 = nj * 32;
    int m0b = wid * 8;

    // shuffle-scatter constants
    bool lead = ((lane & 1) == 0);
    int colB = n0 + ((lane & 2) << 1);   // even lane's v4 column base within its 8-col group

    for (int i = 0; i < nTiles; i++) {
        int rows_i = min(128, rem - i * 128);
        const int* nodeT = nodeG + i * 128;

        // ---- build A(i): h = (rbf @ w_rbf^T) * x -> fp16 ----
        #pragma unroll 2
        for (int m = 0; m < 8; m++) {
            int r = m0b + m;
            bool act = (r < rows_i);
            const float* xr = (const float*)(sm + SM_XBUF + r * 512);
            float rq0 = sRbf[r * 6 + 0], rq1 = sRbf[r * 6 + 1], rq2 = sRbf[r * 6 + 2];
            float rq3 = sRbf[r * 6 + 3], rq4 = sRbf[r * 6 + 4], rq5 = sRbf[r * 6 + 5];
            float4 g;
            g.x = rq0*wq[0].x + rq1*wq[1].x + rq2*wq[2].x + rq3*wq[3].x + rq4*wq[4].x + rq5*wq[5].x;
            g.y = rq0*wq[0].y + rq1*wq[1].y + rq2*wq[2].y + rq3*wq[3].y + rq4*wq[4].y + rq5*wq[5].y;
            g.z = rq0*wq[0].z + rq1*wq[1].z + rq2*wq[2].z + rq3*wq[3].z + rq4*wq[4].z + rq5*wq[5].z;
            g.w = rq0*wq[0].w + rq1*wq[1].w + rq2*wq[2].w + rq3*wq[3].w + rq4*wq[4].w + rq5*wq[5].w;
            float4 xv = *(const float4*)&xr[c0];
            float h0 = act ? g.x * xv.x : 0.f;
            float h1 = act ? g.y * xv.y : 0.f;
            float h2 = act ? g.z * xv.z : 0.f;
            float h3 = act ? g.w * xv.w : 0.f;
            if (s < 8) {
                uint32_t off = (uint32_t)r * RSTRIDE_B + (uint32_t)c0 * 2;
                *(uint32_t*)(sm + SM_AHI + off)     = pack_half2(h0, h1);
                *(uint32_t*)(sm + SM_AHI + off + 4) = pack_half2(h2, h3);
            } else if (act) {
                red_add_v4((float*)g_accum4 + (size_t)nodeT[r] * H + c0, h0, h1, h2, h3);
            }
        }
        __syncthreads();

        // prefetch next tile while MMA runs
        if (i + 1 < nTiles) issue_tile(x, rbf, permG + (i + 1) * 128, sbase, t);
        CP_COMMIT();

        if (s < 8) {
            float acc[2][4][4];
            #pragma unroll
            for (int mt = 0; mt < 2; mt++)
                #pragma unroll
                for (int j = 0; j < 4; j++)
                    acc[mt][j][0] = acc[mt][j][1] = acc[mt][j][2] = acc[mt][j][3] = 0.f;

            mma_pass32_fp(acc, sbase + SM_AHI, sbase + SM_BHI, lane, m0, n0);

            // ---- shuffle-combined v4 scatter (no smem staging) ----
            int rBase = m0 + (lane >> 2);
            #pragma unroll
            for (int mt = 0; mt < 2; mt++) {
                int r0 = rBase + mt * 16, r1 = r0 + 8;
                bool a0 = (r0 < rows_i), a1 = (r1 < rows_i);
                float* p0 = (float*)g_accum4 + (size_t)nodeT[r0] * H;
                float* p1 = (float*)g_accum4 + (size_t)nodeT[r1] * H;
                #pragma unroll
                for (int j = 0; j < 4; j++) {
                    float b0 = __shfl_xor_sync(0xffffffffu, acc[mt][j][0], 1);
                    float b1 = __shfl_xor_sync(0xffffffffu, acc[mt][j][1], 1);
                    float b2 = __shfl_xor_sync(0xffffffffu, acc[mt][j][2], 1);
                    float b3 = __shfl_xor_sync(0xffffffffu, acc[mt][j][3], 1);
                    if (lead) {
                        int col = colB + j * 8;
                        if (a0) red_add_v4(p0 + col, acc[mt][j][0], acc[mt][j][1], b0, b1);
                        if (a1) red_add_v4(p1 + col, acc[mt][j][2], acc[mt][j][3], b2, b3);
                    }
                }
            }
        }
        CP_WAIT0();
        __syncthreads();
    }
}

// ---------------- kernel: fused node MLP (fp16 2-pass, single W buffer, 2 CTAs/SM) ----------------
#define MSM_BIAS 0
#define MSM_A    1536
#define MSM_W    (MSM_A + 34816)            // hi at +0, lo at +34816
#define MLP_SMEM_BYTES (MSM_W + 69632)      // 105,984 B -> 2 CTAs/SM

__device__ __forceinline__ void issue_weight(int slot, uint32_t sbase, int t) {
    const char* srcH = (const char*)&g_wsp_hi[slot][0][0];
    const char* srcL = (const char*)&g_wsp_lo[slot][0][0];
    uint32_t dst = sbase + MSM_W;
    for (int i = t * 16; i < 34816; i += THREADS_M * 16) {
        CP16(dst + i, srcH + i);
        CP16(dst + 34816 + i, srcL + i);
    }
}

__global__ void __launch_bounds__(THREADS_M, 2)
k_mlp(const float* __restrict__ b1, const float* __restrict__ b2,
      const float* __restrict__ b3, float* __restrict__ out, int N)
{
    extern __shared__ char sm[];
    float* sBias = (float*)(sm + MSM_BIAS);
    uint32_t sbase = smem_u32(sm);
    int t = threadIdx.x, wid = t >> 5, lane = t & 31;
    int nb = blockIdx.x * 128;
    int rows = min(128, N - nb);

    issue_weight(8, sbase, t);
    CP_COMMIT();

    // load accumulator rows -> plain fp16 A tile
    const float* accum = (const float*)g_accum4;
    for (int idx = t; idx < 128 * 32; idx += THREADS_M) {
        int r = idx >> 5, c4 = (idx & 31) * 4;
        float4 v = (r < rows) ? *(const float4*)&accum[(size_t)(nb + r) * H + c4]
                              : make_float4(0.f, 0.f, 0.f, 0.f);
        uint32_t off = (uint32_t)r * RSTRIDE_B + (uint32_t)c4 * 2;
        *(uint32_t*)(sm + MSM_A + off)     = pack_half2(v.x, v.y);
        *(uint32_t*)(sm + MSM_A + off + 4) = pack_half2(v.z, v.w);
    }
    if (t < 128) {
        sBias[t]       = b1[t];
        sBias[t + 128] = b2[t];
        sBias[t + 256] = b3[t];
    }

    int m0 = wid * 16;
    int r0 = m0 + (lane >> 2), r1 = r0 + 8, cb = (lane & 3) * 2;

    for (int l = 0; l < 4; l++) {
        CP_WAIT0();        // weight buffer for layer l ready
        __syncthreads();   // + A writes (initial load or previous epilogue) visible

        float acc[16][4];
        #pragma unroll
        for (int j = 0; j < 16; j++) { acc[j][0] = acc[j][1] = acc[j][2] = acc[j][3] = 0.f; }
        mma_stripe_fp(acc, sbase + MSM_A, sbase + MSM_W,         lane, m0);   // A*Wh
        mma_stripe_fp(acc, sbase + MSM_A, sbase + MSM_W + 34816, lane, m0);   // A*Wl
        __syncthreads();   // all W + A reads done

        if (l < 3) { issue_weight(9 + l, sbase, t); CP_COMMIT(); }  // overlap with epilogue

        if (l < 3) {
            const float* bias = sBias + l * 128;
            #pragma unroll
            for (int j = 0; j < 16; j++) {
                int col = j * 8 + cb;
                float v0 = acc[j][0] + bias[col];
                float v1 = acc[j][1] + bias[col + 1];
                float v2 = acc[j][2] + bias[col];
                float v3 = acc[j][3] + bias[col + 1];
                v0 = v0 / (1.f + __expf(-v0));
                v1 = v1 / (1.f + __expf(-v1));
                v2 = v2 / (1.f + __expf(-v2));
                v3 = v3 / (1.f + __expf(-v3));
                uint32_t off0 = (uint32_t)r0 * RSTRIDE_B + (uint32_t)col * 2;
                uint32_t off1 = (uint32_t)r1 * RSTRIDE_B + (uint32_t)col * 2;
                *(uint32_t*)(sm + MSM_A + off0) = pack_half2(v0, v1);
                *(uint32_t*)(sm + MSM_A + off1) = pack_half2(v2, v3);
            }
        } else {
            #pragma unroll
            for (int j = 0; j < 16; j++) {
                int col = j * 8 + cb;
                if (r0 < rows)
                    *(float2*)&out[(size_t)(nb + r0) * H + col] = make_float2(acc[j][0], acc[j][1]);
                if (r1 < rows)
                    *(float2*)&out[(size_t)(nb + r1) * H + col] = make_float2(acc[j][2], acc[j][3]);
            }
        }
    }
}

// ---------------- launcher ----------------
extern "C" void kernel_launch(void* const* d_in, const int* in_sizes, int n_in,
                              void* d_out, int out_size)
{
    const float* x    = (const float*)d_in[0];
    const float* rbf  = (const float*)d_in[1];
    const int*   ei   = (const int*)  d_in[2];
    const float* dist = (const float*)d_in[3];
    int k = 4;
    while (k < n_in && in_sizes[k] != 768) k++;
    const float* w_rbf = (const float*)d_in[k];
    const float* sel_w = (const float*)d_in[k + 1];
    const float* w1    = (const float*)d_in[k + 2];
    const float* b1    = (const float*)d_in[k + 3];
    const float* w2    = (const float*)d_in[k + 4];
    const float* b2    = (const float*)d_in[k + 5];
    const float* w3    = (const float*)d_in[k + 6];
    const float* b3    = (const float*)d_in[k + 7];
    const float* wout  = (const float*)d_in[k + 8];

    int E = in_sizes[0] / H;
    int N = out_size / H;

    cudaFuncSetAttribute(k_edge, cudaFuncAttributeMaxDynamicSharedMemorySize, EDGE_SMEM_BYTES);
    cudaFuncSetAttribute(k_mlp,  cudaFuncAttributeMaxDynamicSharedMemorySize, MLP_SMEM_BYTES);

    k_zero<<<512, 256>>>(N * (H / 4));
    k_hist<<<1024, 256>>>(dist, E);
    k_scan<<<1, 1>>>();
    k_scatter<<<1024, 256>>>(dist, E);
    k_wprep<<<12, 256>>>(sel_w, w1, w2, w3, wout);

    int maxGroups = (E + G_TILES * 128 - 1) / (G_TILES * 128) + NBUCKETS;
    k_edge<<<maxGroups, THREADS_E, EDGE_SMEM_BYTES>>>(x, rbf, ei, w_rbf);
    k_mlp<<<(N + 127) / 128, THREADS_M, MLP_SMEM_BYTES>>>(b1, b2, b3, (float*)d_out, N);
}

// round 13
// speedup vs baseline: 1.0313x; 1.0313x over previous
#include <cuda_runtime.h>
#include <cuda_bf16.h>
#include <cuda_fp16.h>
#include <cstdint>

#define H 128
#define NBUCKETS 9
#define THREADS_E 256
#define THREADS_M 256
#define TILE_E 64        // edge tile rows
#define G_TILES 16       // tiles per group (same 1024 rows/group as before)

#define RSTRIDE_E 136    // elems; 272B rows, 17*16B -> ldmatrix conflict-free
#define RSTRIDE_B 272

// ---------------- device scratch ----------------
__device__ float4 g_accum4[100000 * (H / 4)];
__device__ int    g_perm[1000000];
__device__ int    g_hist[16];
__device__ int    g_start[NBUCKETS];
__device__ int    g_count[NBUCKETS];
__device__ int    g_cursor[NBUCKETS];
__device__ int    g_groupOff[NBUCKETS + 1];
// slots 0..7 experts (fp16, B^T[n][k]=W[k][n]); 8..11 = MLP w1,w2,w3,wout (fp16 hi/lo)
__device__ __align__(16) unsigned short g_wsp_hi[12][128][RSTRIDE_E];
__device__ __align__(16) unsigned short g_wsp_lo[12][128][RSTRIDE_E];

// ---------------- helpers ----------------
__device__ __forceinline__ int bucket_of(float d) {
    float t = (d - 0.8f) / 5.0001f * 8.0f;
    float f = floorf(t);
    return (f >= 0.0f && f < 8.0f) ? (int)f : 8;
}

__device__ __forceinline__ void red_add_v4(float* p, float a, float b, float c, float d) {
    asm volatile("red.global.add.v4.f32 [%0], {%1,%2,%3,%4};"
                 :: "l"(p), "f"(a), "f"(b), "f"(c), "f"(d) : "memory");
}

__device__ __forceinline__ uint32_t smem_u32(const void* p) {
    uint32_t a;
    asm("{ .reg .u64 t; cvta.to.shared.u64 t, %1; cvt.u32.u64 %0, t; }" : "=r"(a) : "l"(p));
    return a;
}

#define CP16(dst, src) asm volatile("cp.async.cg.shared.global [%0], [%1], 16;" :: "r"(dst), "l"(src))
#define CP8(dst, src)  asm volatile("cp.async.ca.shared.global [%0], [%1], 8;"  :: "r"(dst), "l"(src))
#define CP_COMMIT()    asm volatile("cp.async.commit_group;" ::: "memory")
#define CP_WAIT0()     asm volatile("cp.async.wait_group 0;" ::: "memory")

__device__ __forceinline__ void ldsm_x4(uint32_t& r0, uint32_t& r1, uint32_t& r2, uint32_t& r3,
                                        uint32_t addr) {
    asm volatile("ldmatrix.sync.aligned.m8n8.x4.shared.b16 {%0,%1,%2,%3}, [%4];"
                 : "=r"(r0), "=r"(r1), "=r"(r2), "=r"(r3) : "r"(addr));
}

__device__ __forceinline__ void mma_fp16(float* d, uint32_t a0, uint32_t a1, uint32_t a2,
                                         uint32_t a3, uint32_t b0, uint32_t b1) {
    asm volatile("mma.sync.aligned.m16n8k16.row.col.f32.f16.f16.f32 "
                 "{%0,%1,%2,%3}, {%4,%5,%6,%7}, {%8,%9}, {%0,%1,%2,%3};"
                 : "+f"(d[0]), "+f"(d[1]), "+f"(d[2]), "+f"(d[3])
                 : "r"(a0), "r"(a1), "r"(a2), "r"(a3), "r"(b0), "r"(b1));
}

__device__ __forceinline__ uint32_t pack_half2(float v0, float v1) {
    __half h0 = __float2half_rn(v0), h1 = __float2half_rn(v1);
    return (uint32_t)__half_as_ushort(h0) | ((uint32_t)__half_as_ushort(h1) << 16);
}

// fp16 pass for k_mlp: acc[16][4] += A(16x128 stripe at m0) * B^T(128x128)
__device__ __forceinline__ void mma_stripe_fp(float (*acc)[4], uint32_t aBase, uint32_t bBase,
                                              int lane, int m0) {
    uint32_t aAddr = aBase + (uint32_t)(m0 + (lane & 15)) * RSTRIDE_B
                   + (uint32_t)((lane >> 4) << 4);
    uint32_t bAddr = bBase + (uint32_t)((lane & 7) + ((lane >> 4) << 3)) * RSTRIDE_B
                   + (uint32_t)(((lane >> 3) & 1) << 4);
    #pragma unroll
    for (int k0 = 0; k0 < 8; k0++) {
        uint32_t a0, a1, a2, a3;
        ldsm_x4(a0, a1, a2, a3, aAddr + k0 * 32);
        #pragma unroll
        for (int j2 = 0; j2 < 8; j2++) {
            uint32_t b0, b1, b2, b3;
            ldsm_x4(b0, b1, b2, b3, bAddr + j2 * (16 * RSTRIDE_B) + k0 * 32);
            mma_fp16(acc[j2 * 2],     a0, a1, a2, a3, b0, b1);
            mma_fp16(acc[j2 * 2 + 1], a0, a1, a2, a3, b2, b3);
        }
    }
}

// 32x32 warp tile, fp16: acc[2][4][4] += A(32 rows at m0) * B^T(32 cols at n0)
__device__ __forceinline__ void mma_pass32_fp(float (*acc)[4][4], uint32_t aBase, uint32_t bBase,
                                              int lane, int m0, int n0) {
    uint32_t aAddr = aBase + (uint32_t)(m0 + (lane & 15)) * RSTRIDE_B
                   + (uint32_t)((lane >> 4) << 4);
    uint32_t bAddr = bBase + (uint32_t)(n0 + (lane & 7) + ((lane >> 4) << 3)) * RSTRIDE_B
                   + (uint32_t)(((lane >> 3) & 1) << 4);
    #pragma unroll
    for (int k0 = 0; k0 < 8; k0++) {
        uint32_t a0, a1, a2, a3, c0, c1, c2, c3;
        ldsm_x4(a0, a1, a2, a3, aAddr + k0 * 32);
        ldsm_x4(c0, c1, c2, c3, aAddr + 16 * RSTRIDE_B + k0 * 32);
        #pragma unroll
        for (int j2 = 0; j2 < 2; j2++) {
            uint32_t b0, b1, b2, b3;
            ldsm_x4(b0, b1, b2, b3, bAddr + j2 * (16 * RSTRIDE_B) + k0 * 32);
            mma_fp16(acc[0][j2 * 2],     a0, a1, a2, a3, b0, b1);
            mma_fp16(acc[0][j2 * 2 + 1], a0, a1, a2, a3, b2, b3);
            mma_fp16(acc[1][j2 * 2],     c0, c1, c2, c3, b0, b1);
            mma_fp16(acc[1][j2 * 2 + 1], c0, c1, c2, c3, b2, b3);
        }
    }
}

// ---------------- small kernels ----------------
__global__ void k_zero(int n4) {
    int i = blockIdx.x * blockDim.x + threadIdx.x;
    int stride = gridDim.x * blockDim.x;
    float4 z = make_float4(0.f, 0.f, 0.f, 0.f);
    for (; i < n4; i += stride) g_accum4[i] = z;
    if (blockIdx.x == 0 && threadIdx.x < 16) g_hist[threadIdx.x] = 0;
}

__global__ void k_hist(const float* __restrict__ dist, int E) {
    __shared__ int lh[NBUCKETS];
    if (threadIdx.x < NBUCKETS) lh[threadIdx.x] = 0;
    __syncthreads();
    int i = blockIdx.x * blockDim.x + threadIdx.x;
    int stride = gridDim.x * blockDim.x;
    for (; i < E; i += stride) atomicAdd(&lh[bucket_of(dist[i])], 1);
    __syncthreads();
    if (threadIdx.x < NBUCKETS) atomicAdd(&g_hist[threadIdx.x], lh[threadIdx.x]);
}

__global__ void k_scan() {
    if (threadIdx.x == 0 && blockIdx.x == 0) {
        int off = 0, goff = 0;
        for (int s = 0; s < NBUCKETS; s++) {
            int c = g_hist[s];
            g_start[s] = off; g_cursor[s] = off; g_count[s] = c;
            g_groupOff[s] = goff;
            off += c;
            goff += (c + G_TILES * TILE_E - 1) / (G_TILES * TILE_E);
        }
        g_groupOff[NBUCKETS] = goff;
    }
}

__global__ void k_scatter(const float* __restrict__ dist, int E) {
    int lane = threadIdx.x & 31;
    unsigned ltmask = (1u << lane) - 1u;
    int i = blockIdx.x * blockDim.x + threadIdx.x;
    int stride = gridDim.x * blockDim.x;
    for (; i < E; i += stride) {
        int s = bucket_of(dist[i]);
        unsigned m = __match_any_sync(0xffffffffu, s);
        int leader = __ffs(m) - 1;
        int base = 0;
        if (lane == leader) base = atomicAdd(&g_cursor[s], __popc(m));
        base = __shfl_sync(0xffffffffu, base, leader);
        g_perm[base + __popc(m & ltmask)] = i;
    }
}

__global__ void k_wprep(const float* __restrict__ sel_w, const float* __restrict__ w1,
                        const float* __restrict__ w2, const float* __restrict__ w3,
                        const float* __restrict__ wout) {
    int slot = blockIdx.x;
    const float* src;
    bool tr;
    if (slot < 8) { src = sel_w + (size_t)slot * (H * H); tr = true; }
    else {
        const float* m[4] = {w1, w2, w3, wout};
        src = m[slot - 8]; tr = false;
    }
    for (int idx = threadIdx.x; idx < H * H; idx += blockDim.x) {
        int n = idx >> 7, k = idx & 127;
        float w = tr ? src[k * H + n] : src[n * H + k];
        if (slot < 8) {
            g_wsp_hi[slot][n][k] = __half_as_ushort(__float2half_rn(w));
        } else {   // fp16 split-2 for MLP (2-pass)
            __half hh = __float2half_rn(w);
            __half ll = __float2half_rn(w - __half2float(hh));
            g_wsp_hi[slot][n][k] = __half_as_ushort(hh);
            g_wsp_lo[slot][n][k] = __half_as_ushort(ll);
        }
    }
}

// ---------------- kernel: edge expert GEMM (64-row tiles, 256t, 2 CTAs/SM) ----------------
#define SM_META 0
#define SM_WT   32                        // 768 floats
#define SM_PERM (SM_WT + 3072)            // 1024 ints
#define SM_NODE (SM_PERM + 4096)
#define SM_RBF  (SM_NODE + 4096)          // 64*6 floats
#define SM_XBUF (SM_RBF + 1536 + 32)      // 64 rows x 512B = 32768
#define SM_AHI  (SM_XBUF + 32768)         // 64 x 272B = 17408
#define SM_BHI  (SM_AHI + 17408)          // 128 x 272B = 34816
#define EDGE_SMEM_BYTES (SM_BHI + 34816)  // ~96 KB -> 2 CTAs/SM

__device__ __forceinline__ void issue_tile(const float* x, const float* rbf,
                                           const int* pt, uint32_t sbase, int t) {
    #pragma unroll 4
    for (int idx = t; idx < 2048; idx += THREADS_E) {
        int r = idx >> 5, seg = idx & 31;
        const char* src = (const char*)(x + (size_t)pt[r] * H) + seg * 16;
        CP16(sbase + SM_XBUF + r * 512 + seg * 16, src);
    }
    if (t < 192) {
        int r = t / 3, p = t - r * 3;
        const char* src = (const char*)(rbf + (size_t)pt[r] * 6) + p * 8;
        CP8(sbase + SM_RBF + r * 24 + p * 8, src);
    }
}

__global__ void __launch_bounds__(THREADS_E, 2)
k_edge(const float* __restrict__ x, const float* __restrict__ rbf,
       const int* __restrict__ eidx, const float* __restrict__ w_rbf)
{
    extern __shared__ char sm[];
    int*   meta  = (int*)(sm + SM_META);
    float* sWT   = (float*)(sm + SM_WT);
    int*   permG = (int*)(sm + SM_PERM);
    int*   nodeG = (int*)(sm + SM_NODE);
    float* sRbf  = (float*)(sm + SM_RBF);
    uint32_t sbase = smem_u32(sm);

    int t = threadIdx.x, wid = t >> 5, lane = t & 31;

    if (t == 0) {
        int b = blockIdx.x;
        int found = -1, grpLocal = 0;
        if (b < g_groupOff[NBUCKETS]) {
            #pragma unroll
            for (int q = 0; q < NBUCKETS; q++)
                if (b >= g_groupOff[q] && b < g_groupOff[q + 1]) { found = q; grpLocal = b - g_groupOff[q]; }
        }
        if (found < 0) meta[0] = -1;
        else {
            int rowBase = grpLocal * (G_TILES * TILE_E);
            int rem = g_count[found] - rowBase;
            if (rem > G_TILES * TILE_E) rem = G_TILES * TILE_E;
            meta[0] = found;
            meta[1] = (rem + TILE_E - 1) / TILE_E;
            meta[2] = g_start[found] + rowBase;
            meta[3] = rem;
        }
    }
    __syncthreads();
    int s = meta[0];
    if (s < 0) return;
    int nTiles = meta[1], rowStart = meta[2], rem = meta[3];

    for (int idx = t; idx < nTiles * TILE_E; idx += THREADS_E)
        permG[idx] = (idx < rem) ? g_perm[rowStart + idx] : g_perm[rowStart];
    for (int idx = t; idx < 768; idx += THREADS_E) {
        int q = idx >> 7, c = idx & 127;
        sWT[idx] = w_rbf[c * 6 + q];
    }
    __syncthreads();
    for (int idx = t; idx < nTiles * TILE_E; idx += THREADS_E)
        nodeG[idx] = eidx[permG[idx]];

    if (s < 8) {   // expert weight (fp16), once per group
        const char* srcH = (const char*)&g_wsp_hi[s][0][0];
        for (int i = t * 16; i < 34816; i += THREADS_E * 16)
            CP16(sbase + SM_BHI + i, srcH + i);
    }
    issue_tile(x, rbf, permG, sbase, t);
    CP_COMMIT();
    CP_WAIT0();
    __syncthreads();

    int c0 = lane * 4;
    float4 wq[6];
    #pragma unroll
    for (int q = 0; q < 6; q++) wq[q] = *(float4*)&sWT[q * 128 + c0];

    int mi = wid & 1, nj = wid >> 1;          // 2x4 warp grid over 64x128
    int m0 = mi * 32, n0 = nj * 32;
    int m0b = wid * 8;                         // build: 8 rows per warp

    // shuffle-scatter constants
    bool lead = ((lane & 1) == 0);
    int colB = n0 + ((lane & 2) << 1);

    for (int i = 0; i < nTiles; i++) {
        int rows_i = min(TILE_E, rem - i * TILE_E);
        const int* nodeT = nodeG + i * TILE_E;

        // ---- build A(i): h = (rbf @ w_rbf^T) * x -> fp16 ----
        #pragma unroll 2
        for (int m = 0; m < 8; m++) {
            int r = m0b + m;
            bool act = (r < rows_i);
            const float* xr = (const float*)(sm + SM_XBUF + r * 512);
            float rq0 = sRbf[r * 6 + 0], rq1 = sRbf[r * 6 + 1], rq2 = sRbf[r * 6 + 2];
            float rq3 = sRbf[r * 6 + 3], rq4 = sRbf[r * 6 + 4], rq5 = sRbf[r * 6 + 5];
            float4 g;
            g.x = rq0*wq[0].x + rq1*wq[1].x + rq2*wq[2].x + rq3*wq[3].x + rq4*wq[4].x + rq5*wq[5].x;
            g.y = rq0*wq[0].y + rq1*wq[1].y + rq2*wq[2].y + rq3*wq[3].y + rq4*wq[4].y + rq5*wq[5].y;
            g.z = rq0*wq[0].z + rq1*wq[1].z + rq2*wq[2].z + rq3*wq[3].z + rq4*wq[4].z + rq5*wq[5].z;
            g.w = rq0*wq[0].w + rq1*wq[1].w + rq2*wq[2].w + rq3*wq[3].w + rq4*wq[4].w + rq5*wq[5].w;
            float4 xv = *(const float4*)&xr[c0];
            float h0 = act ? g.x * xv.x : 0.f;
            float h1 = act ? g.y * xv.y : 0.f;
            float h2 = act ? g.z * xv.z : 0.f;
            float h3 = act ? g.w * xv.w : 0.f;
            if (s < 8) {
                uint32_t off = (uint32_t)r * RSTRIDE_B + (uint32_t)c0 * 2;
                *(uint32_t*)(sm + SM_AHI + off)     = pack_half2(h0, h1);
                *(uint32_t*)(sm + SM_AHI + off + 4) = pack_half2(h2, h3);
            } else if (act) {
                red_add_v4((float*)g_accum4 + (size_t)nodeT[r] * H + c0, h0, h1, h2, h3);
            }
        }
        __syncthreads();

        // prefetch next tile while MMA runs
        if (i + 1 < nTiles) issue_tile(x, rbf, permG + (i + 1) * TILE_E, sbase, t);
        CP_COMMIT();

        if (s < 8) {
            float acc[2][4][4];
            #pragma unroll
            for (int mt = 0; mt < 2; mt++)
                #pragma unroll
                for (int j = 0; j < 4; j++)
                    acc[mt][j][0] = acc[mt][j][1] = acc[mt][j][2] = acc[mt][j][3] = 0.f;

            mma_pass32_fp(acc, sbase + SM_AHI, sbase + SM_BHI, lane, m0, n0);

            // ---- shuffle-combined v4 scatter (other CTA hides this latency) ----
            int rBase = m0 + (lane >> 2);
            #pragma unroll
            for (int mt = 0; mt < 2; mt++) {
                int r0 = rBase + mt * 16, r1 = r0 + 8;
                bool a0 = (r0 < rows_i), a1 = (r1 < rows_i);
                float* p0 = (float*)g_accum4 + (size_t)nodeT[r0] * H;
                float* p1 = (float*)g_accum4 + (size_t)nodeT[r1] * H;
                #pragma unroll
                for (int j = 0; j < 4; j++) {
                    float b0 = __shfl_xor_sync(0xffffffffu, acc[mt][j][0], 1);
                    float b1 = __shfl_xor_sync(0xffffffffu, acc[mt][j][1], 1);
                    float b2 = __shfl_xor_sync(0xffffffffu, acc[mt][j][2], 1);
                    float b3 = __shfl_xor_sync(0xffffffffu, acc[mt][j][3], 1);
                    if (lead) {
                        int col = colB + j * 8;
                        if (a0) red_add_v4(p0 + col, acc[mt][j][0], acc[mt][j][1], b0, b1);
                        if (a1) red_add_v4(p1 + col, acc[mt][j][2], acc[mt][j][3], b2, b3);
                    }
                }
            }
        }
        CP_WAIT0();
        __syncthreads();
    }
}

// ---------------- kernel: fused node MLP (fp16 2-pass, single W buffer, 2 CTAs/SM) ----------------
#define MSM_BIAS 0
#define MSM_A    1536
#define MSM_W    (MSM_A + 34816)            // hi at +0, lo at +34816
#define MLP_SMEM_BYTES (MSM_W + 69632)      // 105,984 B -> 2 CTAs/SM

__device__ __forceinline__ void issue_weight(int slot, uint32_t sbase, int t) {
    const char* srcH = (const char*)&g_wsp_hi[slot][0][0];
    const char* srcL = (const char*)&g_wsp_lo[slot][0][0];
    uint32_t dst = sbase + MSM_W;
    for (int i = t * 16; i < 34816; i += THREADS_M * 16) {
        CP16(dst + i, srcH + i);
        CP16(dst + 34816 + i, srcL + i);
    }
}

__global__ void __launch_bounds__(THREADS_M, 2)
k_mlp(const float* __restrict__ b1, const float* __restrict__ b2,
      const float* __restrict__ b3, float* __restrict__ out, int N)
{
    extern __shared__ char sm[];
    float* sBias = (float*)(sm + MSM_BIAS);
    uint32_t sbase = smem_u32(sm);
    int t = threadIdx.x, wid = t >> 5, lane = t & 31;
    int nb = blockIdx.x * 128;
    int rows = min(128, N - nb);

    issue_weight(8, sbase, t);
    CP_COMMIT();

    // load accumulator rows -> plain fp16 A tile
    const float* accum = (const float*)g_accum4;
    for (int idx = t; idx < 128 * 32; idx += THREADS_M) {
        int r = idx >> 5, c4 = (idx & 31) * 4;
        float4 v = (r < rows) ? *(const float4*)&accum[(size_t)(nb + r) * H + c4]
                              : make_float4(0.f, 0.f, 0.f, 0.f);
        uint32_t off = (uint32_t)r * RSTRIDE_B + (uint32_t)c4 * 2;
        *(uint32_t*)(sm + MSM_A + off)     = pack_half2(v.x, v.y);
        *(uint32_t*)(sm + MSM_A + off + 4) = pack_half2(v.z, v.w);
    }
    if (t < 128) {
        sBias[t]       = b1[t];
        sBias[t + 128] = b2[t];
        sBias[t + 256] = b3[t];
    }

    int m0 = wid * 16;
    int r0 = m0 + (lane >> 2), r1 = r0 + 8, cb = (lane & 3) * 2;

    for (int l = 0; l < 4; l++) {
        CP_WAIT0();        // weight buffer for layer l ready
        __syncthreads();   // + A writes (initial load or previous epilogue) visible

        float acc[16][4];
        #pragma unroll
        for (int j = 0; j < 16; j++) { acc[j][0] = acc[j][1] = acc[j][2] = acc[j][3] = 0.f; }
        mma_stripe_fp(acc, sbase + MSM_A, sbase + MSM_W,         lane, m0);   // A*Wh
        mma_stripe_fp(acc, sbase + MSM_A, sbase + MSM_W + 34816, lane, m0);   // A*Wl
        __syncthreads();   // all W + A reads done

        if (l < 3) { issue_weight(9 + l, sbase, t); CP_COMMIT(); }  // overlap with epilogue

        if (l < 3) {
            const float* bias = sBias + l * 128;
            #pragma unroll
            for (int j = 0; j < 16; j++) {
                int col = j * 8 + cb;
                float v0 = acc[j][0] + bias[col];
                float v1 = acc[j][1] + bias[col + 1];
                float v2 = acc[j][2] + bias[col];
                float v3 = acc[j][3] + bias[col + 1];
                v0 = v0 / (1.f + __expf(-v0));
                v1 = v1 / (1.f + __expf(-v1));
                v2 = v2 / (1.f + __expf(-v2));
                v3 = v3 / (1.f + __expf(-v3));
                uint32_t off0 = (uint32_t)r0 * RSTRIDE_B + (uint32_t)col * 2;
                uint32_t off1 = (uint32_t)r1 * RSTRIDE_B + (uint32_t)col * 2;
                *(uint32_t*)(sm + MSM_A + off0) = pack_half2(v0, v1);
                *(uint32_t*)(sm + MSM_A + off1) = pack_half2(v2, v3);
            }
        } else {
            #pragma unroll
            for (int j = 0; j < 16; j++) {
                int col = j * 8 + cb;
                if (r0 < rows)
                    *(float2*)&out[(size_t)(nb + r0) * H + col] = make_float2(acc[j][0], acc[j][1]);
                if (r1 < rows)
                    *(float2*)&out[(size_t)(nb + r1) * H + col] = make_float2(acc[j][2], acc[j][3]);
            }
        }
    }
}

// ---------------- launcher ----------------
extern "C" void kernel_launch(void* const* d_in, const int* in_sizes, int n_in,
                              void* d_out, int out_size)
{
    const float* x    = (const float*)d_in[0];
    const float* rbf  = (const float*)d_in[1];
    const int*   ei   = (const int*)  d_in[2];
    const float* dist = (const float*)d_in[3];
    int k = 4;
    while (k < n_in && in_sizes[k] != 768) k++;
    const float* w_rbf = (const float*)d_in[k];
    const float* sel_w = (const float*)d_in[k + 1];
    const float* w1    = (const float*)d_in[k + 2];
    const float* b1    = (const float*)d_in[k + 3];
    const float* w2    = (const float*)d_in[k + 4];
    const float* b2    = (const float*)d_in[k + 5];
    const float* w3    = (const float*)d_in[k + 6];
    const float* b3    = (const float*)d_in[k + 7];
    const float* wout  = (const float*)d_in[k + 8];

    int E = in_sizes[0] / H;
    int N = out_size / H;

    cudaFuncSetAttribute(k_edge, cudaFuncAttributeMaxDynamicSharedMemorySize, EDGE_SMEM_BYTES);
    cudaFuncSetAttribute(k_mlp,  cudaFuncAttributeMaxDynamicSharedMemorySize, MLP_SMEM_BYTES);

    k_zero<<<512, 256>>>(N * (H / 4));
    k_hist<<<1024, 256>>>(dist, E);
    k_scan<<<1, 1>>>();
    k_scatter<<<1024, 256>>>(dist, E);
    k_wprep<<<12, 256>>>(sel_w, w1, w2, w3, wout);

    int maxGroups = (E + G_TILES * TILE_E - 1) / (G_TILES * TILE_E) + NBUCKETS;
    k_edge<<<maxGroups, THREADS_E, EDGE_SMEM_BYTES>>>(x, rbf, ei, w_rbf);
    k_mlp<<<(N + 127) / 128, THREADS_M, MLP_SMEM_BYTES>>>(b1, b2, b3, (float*)d_out, N);
}

// round 14
// speedup vs baseline: 1.0363x; 1.0049x over previous
#include <cuda_runtime.h>
#include <cuda_bf16.h>
#include <cuda_fp16.h>
#include <cstdint>

#define H 128
#define NBUCKETS 9
#define THREADS_E 512
#define THREADS_M 256
#define G_TILES 8
#define CAP 1000000      // per-bucket capacity in g_permB

#define RSTRIDE_E 136    // elems; 272B rows, 17*16B -> ldmatrix conflict-free
#define RSTRIDE_B 272
#define SD_STRIDE 132

// ---------------- device scratch ----------------
__device__ float4 g_accum4[100000 * (H / 4)];   // zeroed by cudaMemsetAsync each launch
__device__ int    g_permB[NBUCKETS * CAP];      // per-bucket edge lists
__device__ int    g_cnt[16];                    // per-bucket counts (memset each launch)
// slots 0..7 experts (fp16, B^T[n][k]=W[k][n]); 8..11 = MLP w1,w2,w3,wout (fp16 hi/lo)
__device__ __align__(16) unsigned short g_wsp_hi[12][128][RSTRIDE_E];
__device__ __align__(16) unsigned short g_wsp_lo[12][128][RSTRIDE_E];

// ---------------- helpers ----------------
__device__ __forceinline__ int bucket_of(float d) {
    float t = (d - 0.8f) / 5.0001f * 8.0f;
    float f = floorf(t);
    return (f >= 0.0f && f < 8.0f) ? (int)f : 8;
}

__device__ __forceinline__ void red_add_v4(float* p, float a, float b, float c, float d) {
    asm volatile("red.global.add.v4.f32 [%0], {%1,%2,%3,%4};"
                 :: "l"(p), "f"(a), "f"(b), "f"(c), "f"(d) : "memory");
}

__device__ __forceinline__ uint32_t smem_u32(const void* p) {
    uint32_t a;
    asm("{ .reg .u64 t; cvta.to.shared.u64 t, %1; cvt.u32.u64 %0, t; }" : "=r"(a) : "l"(p));
    return a;
}

#define CP16(dst, src) asm volatile("cp.async.cg.shared.global [%0], [%1], 16;" :: "r"(dst), "l"(src))
#define CP8(dst, src)  asm volatile("cp.async.ca.shared.global [%0], [%1], 8;"  :: "r"(dst), "l"(src))
#define CP_COMMIT()    asm volatile("cp.async.commit_group;" ::: "memory")
#define CP_WAIT0()     asm volatile("cp.async.wait_group 0;" ::: "memory")

__device__ __forceinline__ void ldsm_x4(uint32_t& r0, uint32_t& r1, uint32_t& r2, uint32_t& r3,
                                        uint32_t addr) {
    asm volatile("ldmatrix.sync.aligned.m8n8.x4.shared.b16 {%0,%1,%2,%3}, [%4];"
                 : "=r"(r0), "=r"(r1), "=r"(r2), "=r"(r3) : "r"(addr));
}

__device__ __forceinline__ void mma_fp16(float* d, uint32_t a0, uint32_t a1, uint32_t a2,
                                         uint32_t a3, uint32_t b0, uint32_t b1) {
    asm volatile("mma.sync.aligned.m16n8k16.row.col.f32.f16.f16.f32 "
                 "{%0,%1,%2,%3}, {%4,%5,%6,%7}, {%8,%9}, {%0,%1,%2,%3};"
                 : "+f"(d[0]), "+f"(d[1]), "+f"(d[2]), "+f"(d[3])
                 : "r"(a0), "r"(a1), "r"(a2), "r"(a3), "r"(b0), "r"(b1));
}

__device__ __forceinline__ uint32_t pack_half2(float v0, float v1) {
    __half h0 = __float2half_rn(v0), h1 = __float2half_rn(v1);
    return (uint32_t)__half_as_ushort(h0) | ((uint32_t)__half_as_ushort(h1) << 16);
}

// fp16 pass for k_mlp: acc[16][4] += A(16x128 stripe at m0) * B^T(128x128)
__device__ __forceinline__ void mma_stripe_fp(float (*acc)[4], uint32_t aBase, uint32_t bBase,
                                              int lane, int m0) {
    uint32_t aAddr = aBase + (uint32_t)(m0 + (lane & 15)) * RSTRIDE_B
                   + (uint32_t)((lane >> 4) << 4);
    uint32_t bAddr = bBase + (uint32_t)((lane & 7) + ((lane >> 4) << 3)) * RSTRIDE_B
                   + (uint32_t)(((lane >> 3) & 1) << 4);
    #pragma unroll
    for (int k0 = 0; k0 < 8; k0++) {
        uint32_t a0, a1, a2, a3;
        ldsm_x4(a0, a1, a2, a3, aAddr + k0 * 32);
        #pragma unroll
        for (int j2 = 0; j2 < 8; j2++) {
            uint32_t b0, b1, b2, b3;
            ldsm_x4(b0, b1, b2, b3, bAddr + j2 * (16 * RSTRIDE_B) + k0 * 32);
            mma_fp16(acc[j2 * 2],     a0, a1, a2, a3, b0, b1);
            mma_fp16(acc[j2 * 2 + 1], a0, a1, a2, a3, b2, b3);
        }
    }
}

// 32x32 warp tile, fp16: acc[2][4][4] += A(32 rows at m0) * B^T(32 cols at n0)
__device__ __forceinline__ void mma_pass32_fp(float (*acc)[4][4], uint32_t aBase, uint32_t bBase,
                                              int lane, int m0, int n0) {
    uint32_t aAddr = aBase + (uint32_t)(m0 + (lane & 15)) * RSTRIDE_B
                   + (uint32_t)((lane >> 4) << 4);
    uint32_t bAddr = bBase + (uint32_t)(n0 + (lane & 7) + ((lane >> 4) << 3)) * RSTRIDE_B
                   + (uint32_t)(((lane >> 3) & 1) << 4);
    #pragma unroll
    for (int k0 = 0; k0 < 8; k0++) {
        uint32_t a0, a1, a2, a3, c0, c1, c2, c3;
        ldsm_x4(a0, a1, a2, a3, aAddr + k0 * 32);
        ldsm_x4(c0, c1, c2, c3, aAddr + 16 * RSTRIDE_B + k0 * 32);
        #pragma unroll
        for (int j2 = 0; j2 < 2; j2++) {
            uint32_t b0, b1, b2, b3;
            ldsm_x4(b0, b1, b2, b3, bAddr + j2 * (16 * RSTRIDE_B) + k0 * 32);
            mma_fp16(acc[0][j2 * 2],     a0, a1, a2, a3, b0, b1);
            mma_fp16(acc[0][j2 * 2 + 1], a0, a1, a2, a3, b2, b3);
            mma_fp16(acc[1][j2 * 2],     c0, c1, c2, c3, b0, b1);
            mma_fp16(acc[1][j2 * 2 + 1], c0, c1, c2, c3, b2, b3);
        }
    }
}

// ---------------- front-end: direct per-bucket scatter (no hist/scan) ----------------
__global__ void k_scatter(const float* __restrict__ dist, int E) {
    int lane = threadIdx.x & 31;
    unsigned ltmask = (1u << lane) - 1u;
    int i = blockIdx.x * blockDim.x + threadIdx.x;
    int stride = gridDim.x * blockDim.x;
    for (; i < E; i += stride) {
        int s = bucket_of(dist[i]);
        unsigned m = __match_any_sync(0xffffffffu, s);
        int leader = __ffs(m) - 1;
        int base = 0;
        if (lane == leader) base = atomicAdd(&g_cnt[s], __popc(m));
        base = __shfl_sync(0xffffffffu, base, leader);
        g_permB[(size_t)s * CAP + base + __popc(m & ltmask)] = i;
    }
}

__global__ void k_wprep(const float* __restrict__ sel_w, const float* __restrict__ w1,
                        const float* __restrict__ w2, const float* __restrict__ w3,
                        const float* __restrict__ wout) {
    int slot = blockIdx.x;
    const float* src;
    bool tr;
    if (slot < 8) { src = sel_w + (size_t)slot * (H * H); tr = true; }
    else {
        const float* m[4] = {w1, w2, w3, wout};
        src = m[slot - 8]; tr = false;
    }
    for (int idx = threadIdx.x; idx < H * H; idx += blockDim.x) {
        int n = idx >> 7, k = idx & 127;
        float w = tr ? src[k * H + n] : src[n * H + k];
        if (slot < 8) {
            g_wsp_hi[slot][n][k] = __half_as_ushort(__float2half_rn(w));
        } else {   // fp16 split-2 for MLP (2-pass)
            __half hh = __float2half_rn(w);
            __half ll = __float2half_rn(w - __half2float(hh));
            g_wsp_hi[slot][n][k] = __half_as_ushort(hh);
            g_wsp_lo[slot][n][k] = __half_as_ushort(ll);
        }
    }
}

// ---------------- kernel: edge expert GEMM (R11 best: 512t, staged v4 scatter) ----------------
#define SM_META 0
#define SM_WT   32
#define SM_PERM (SM_WT + 3072)
#define SM_NODE (SM_PERM + 4096)
#define SM_RBF  (SM_NODE + 4096)
#define SM_XBUF (SM_RBF + 3072 + 32)
#define SM_AHI  (SM_XBUF + 65536)
#define SM_BHI  (SM_AHI + 34816)
#define SM_DST  (SM_BHI + 34816)
#define EDGE_SMEM_BYTES (SM_DST + 128 * SD_STRIDE * 4)

__device__ __forceinline__ void issue_tile(const float* x, const float* rbf,
                                           const int* pt, uint32_t sbase, int t) {
    #pragma unroll 4
    for (int idx = t; idx < 4096; idx += THREADS_E) {
        int r = idx >> 5, seg = idx & 31;
        const char* src = (const char*)(x + (size_t)pt[r] * H) + seg * 16;
        CP16(sbase + SM_XBUF + r * 512 + seg * 16, src);
    }
    if (t < 384) {
        int r = t / 3, p = t - r * 3;
        const char* src = (const char*)(rbf + (size_t)pt[r] * 6) + p * 8;
        CP8(sbase + SM_RBF + r * 24 + p * 8, src);
    }
}

__global__ void __launch_bounds__(THREADS_E, 1)
k_edge(const float* __restrict__ x, const float* __restrict__ rbf,
       const int* __restrict__ eidx, const float* __restrict__ w_rbf, int maxG)
{
    extern __shared__ char sm[];
    int*   meta  = (int*)(sm + SM_META);
    float* sWT   = (float*)(sm + SM_WT);
    int*   permG = (int*)(sm + SM_PERM);
    int*   nodeG = (int*)(sm + SM_NODE);
    float* sRbf  = (float*)(sm + SM_RBF);
    float* sD    = (float*)(sm + SM_DST);
    uint32_t sbase = smem_u32(sm);

    int t = threadIdx.x, wid = t >> 5, lane = t & 31;

    if (t == 0) {
        int s = blockIdx.x / maxG;
        int grp = blockIdx.x - s * maxG;
        int rowBase = grp * (G_TILES * 128);
        int rem = g_cnt[s] - rowBase;
        if (rem <= 0) meta[0] = -1;
        else {
            if (rem > G_TILES * 128) rem = G_TILES * 128;
            meta[0] = s;
            meta[1] = (rem + 127) >> 7;
            meta[2] = rowBase;
            meta[3] = rem;
        }
    }
    __syncthreads();
    int s = meta[0];
    if (s < 0) return;
    int nTiles = meta[1], rowStart = meta[2], rem = meta[3];
    const int* permSrc = g_permB + (size_t)s * CAP + rowStart;

    for (int idx = t; idx < nTiles * 128; idx += THREADS_E)
        permG[idx] = (idx < rem) ? permSrc[idx] : permSrc[0];
    for (int idx = t; idx < 768; idx += THREADS_E) {
        int q = idx >> 7, c = idx & 127;
        sWT[idx] = w_rbf[c * 6 + q];
    }
    __syncthreads();
    for (int idx = t; idx < nTiles * 128; idx += THREADS_E)
        nodeG[idx] = eidx[permG[idx]];

    if (s < 8) {   // expert weight (fp16), once per group
        const char* srcH = (const char*)&g_wsp_hi[s][0][0];
        for (int i = t * 16; i < 34816; i += THREADS_E * 16)
            CP16(sbase + SM_BHI + i, srcH + i);
    }
    issue_tile(x, rbf, permG, sbase, t);
    CP_COMMIT();
    CP_WAIT0();
    __syncthreads();

    int c0 = lane * 4;
    float4 wq[6];
    #pragma unroll
    for (int q = 0; q < 6; q++) wq[q] = *(float4*)&sWT[q * 128 + c0];

    int mi = wid & 3, nj = wid >> 2;
    int m0 = mi * 32, n0 = nj * 32;
    int m0b = wid * 8;

    for (int i = 0; i < nTiles; i++) {
        int rows_i = min(128, rem - i * 128);
        const int* nodeT = nodeG + i * 128;

        // ---- build A(i): h = (rbf @ w_rbf^T) * x -> fp16 ----
        #pragma unroll 2
        for (int m = 0; m < 8; m++) {
            int r = m0b + m;
            bool act = (r < rows_i);
            const float* xr = (const float*)(sm + SM_XBUF + r * 512);
            float rq0 = sRbf[r * 6 + 0], rq1 = sRbf[r * 6 + 1], rq2 = sRbf[r * 6 + 2];
            float rq3 = sRbf[r * 6 + 3], rq4 = sRbf[r * 6 + 4], rq5 = sRbf[r * 6 + 5];
            float4 g;
            g.x = rq0*wq[0].x + rq1*wq[1].x + rq2*wq[2].x + rq3*wq[3].x + rq4*wq[4].x + rq5*wq[5].x;
            g.y = rq0*wq[0].y + rq1*wq[1].y + rq2*wq[2].y + rq3*wq[3].y + rq4*wq[4].y + rq5*wq[5].y;
            g.z = rq0*wq[0].z + rq1*wq[1].z + rq2*wq[2].z + rq3*wq[3].z + rq4*wq[4].z + rq5*wq[5].z;
            g.w = rq0*wq[0].w + rq1*wq[1].w + rq2*wq[2].w + rq3*wq[3].w + rq4*wq[4].w + rq5*wq[5].w;
            float4 xv = *(const float4*)&xr[c0];
            float h0 = act ? g.x * xv.x : 0.f;
            float h1 = act ? g.y * xv.y : 0.f;
            float h2 = act ? g.z * xv.z : 0.f;
            float h3 = act ? g.w * xv.w : 0.f;
            if (s < 8) {
                uint32_t off = (uint32_t)r * RSTRIDE_B + (uint32_t)c0 * 2;
                *(uint32_t*)(sm + SM_AHI + off)     = pack_half2(h0, h1);
                *(uint32_t*)(sm + SM_AHI + off + 4) = pack_half2(h2, h3);
            } else if (act) {
                red_add_v4((float*)g_accum4 + (size_t)nodeT[r] * H + c0, h0, h1, h2, h3);
            }
        }
        __syncthreads();

        // prefetch next tile while MMA runs
        if (i + 1 < nTiles) issue_tile(x, rbf, permG + (i + 1) * 128, sbase, t);
        CP_COMMIT();

        if (s < 8) {
            float acc[2][4][4];
            #pragma unroll
            for (int mt = 0; mt < 2; mt++)
                #pragma unroll
                for (int j = 0; j < 4; j++)
                    acc[mt][j][0] = acc[mt][j][1] = acc[mt][j][2] = acc[mt][j][3] = 0.f;

            mma_pass32_fp(acc, sbase + SM_AHI, sbase + SM_BHI, lane, m0, n0);

            // stage D (own 32x32 region; no pre-sync)
            int lrBase = m0 + (lane >> 2);
            int cBase = n0 + (lane & 3) * 2;
            #pragma unroll
            for (int mt = 0; mt < 2; mt++) {
                #pragma unroll
                for (int j = 0; j < 4; j++) {
                    int lr = lrBase + mt * 16;
                    int col = cBase + j * 8;
                    *(float2*)&sD[lr * SD_STRIDE + col] =
                        make_float2(acc[mt][j][0], acc[mt][j][1]);
                    *(float2*)&sD[(lr + 8) * SD_STRIDE + col] =
                        make_float2(acc[mt][j][2], acc[mt][j][3]);
                }
            }
            __syncthreads();

            // single-phase red.v4 scatter
            #pragma unroll 4
            for (int idx = t; idx < 4096; idx += THREADS_E) {
                int row = idx >> 5, c4 = (idx & 31) << 2;
                if (row < rows_i) {
                    float4 v = *(float4*)&sD[row * SD_STRIDE + c4];
                    red_add_v4((float*)g_accum4 + (size_t)nodeT[row] * H + c4,
                               v.x, v.y, v.z, v.w);
                }
            }
        }
        CP_WAIT0();
        __syncthreads();
    }
}

// ---------------- kernel: fused node MLP (fp16 2-pass, single W buffer, 2 CTAs/SM) ----------------
#define MSM_BIAS 0
#define MSM_A    1536
#define MSM_W    (MSM_A + 34816)            // hi at +0, lo at +34816
#define MLP_SMEM_BYTES (MSM_W + 69632)      // 105,984 B -> 2 CTAs/SM

__device__ __forceinline__ void issue_weight(int slot, uint32_t sbase, int t) {
    const char* srcH = (const char*)&g_wsp_hi[slot][0][0];
    const char* srcL = (const char*)&g_wsp_lo[slot][0][0];
    uint32_t dst = sbase + MSM_W;
    for (int i = t * 16; i < 34816; i += THREADS_M * 16) {
        CP16(dst + i, srcH + i);
        CP16(dst + 34816 + i, srcL + i);
    }
}

__global__ void __launch_bounds__(THREADS_M, 2)
k_mlp(const float* __restrict__ b1, const float* __restrict__ b2,
      const float* __restrict__ b3, float* __restrict__ out, int N)
{
    extern __shared__ char sm[];
    float* sBias = (float*)(sm + MSM_BIAS);
    uint32_t sbase = smem_u32(sm);
    int t = threadIdx.x, wid = t >> 5, lane = t & 31;
    int nb = blockIdx.x * 128;
    int rows = min(128, N - nb);

    issue_weight(8, sbase, t);
    CP_COMMIT();

    // load accumulator rows -> plain fp16 A tile
    const float* accum = (const float*)g_accum4;
    for (int idx = t; idx < 128 * 32; idx += THREADS_M) {
        int r = idx >> 5, c4 = (idx & 31) * 4;
        float4 v = (r < rows) ? *(const float4*)&accum[(size_t)(nb + r) * H + c4]
                              : make_float4(0.f, 0.f, 0.f, 0.f);
        uint32_t off = (uint32_t)r * RSTRIDE_B + (uint32_t)c4 * 2;
        *(uint32_t*)(sm + MSM_A + off)     = pack_half2(v.x, v.y);
        *(uint32_t*)(sm + MSM_A + off + 4) = pack_half2(v.z, v.w);
    }
    if (t < 128) {
        sBias[t]       = b1[t];
        sBias[t + 128] = b2[t];
        sBias[t + 256] = b3[t];
    }

    int m0 = wid * 16;
    int r0 = m0 + (lane >> 2), r1 = r0 + 8, cb = (lane & 3) * 2;

    for (int l = 0; l < 4; l++) {
        CP_WAIT0();        // weight buffer for layer l ready
        __syncthreads();   // + A writes (initial load or previous epilogue) visible

        float acc[16][4];
        #pragma unroll
        for (int j = 0; j < 16; j++) { acc[j][0] = acc[j][1] = acc[j][2] = acc[j][3] = 0.f; }
        mma_stripe_fp(acc, sbase + MSM_A, sbase + MSM_W,         lane, m0);   // A*Wh
        mma_stripe_fp(acc, sbase + MSM_A, sbase + MSM_W + 34816, lane, m0);   // A*Wl
        __syncthreads();   // all W + A reads done

        if (l < 3) { issue_weight(9 + l, sbase, t); CP_COMMIT(); }  // overlap with epilogue

        if (l < 3) {
            const float* bias = sBias + l * 128;
            #pragma unroll
            for (int j = 0; j < 16; j++) {
                int col = j * 8 + cb;
                float v0 = acc[j][0] + bias[col];
                float v1 = acc[j][1] + bias[col + 1];
                float v2 = acc[j][2] + bias[col];
                float v3 = acc[j][3] + bias[col + 1];
                v0 = v0 / (1.f + __expf(-v0));
                v1 = v1 / (1.f + __expf(-v1));
                v2 = v2 / (1.f + __expf(-v2));
                v3 = v3 / (1.f + __expf(-v3));
                uint32_t off0 = (uint32_t)r0 * RSTRIDE_B + (uint32_t)col * 2;
                uint32_t off1 = (uint32_t)r1 * RSTRIDE_B + (uint32_t)col * 2;
                *(uint32_t*)(sm + MSM_A + off0) = pack_half2(v0, v1);
                *(uint32_t*)(sm + MSM_A + off1) = pack_half2(v2, v3);
            }
        } else {
            #pragma unroll
            for (int j = 0; j < 16; j++) {
                int col = j * 8 + cb;
                if (r0 < rows)
                    *(float2*)&out[(size_t)(nb + r0) * H + col] = make_float2(acc[j][0], acc[j][1]);
                if (r1 < rows)
                    *(float2*)&out[(size_t)(nb + r1) * H + col] = make_float2(acc[j][2], acc[j][3]);
            }
        }
    }
}

// ---------------- launcher ----------------
extern "C" void kernel_launch(void* const* d_in, const int* in_sizes, int n_in,
                              void* d_out, int out_size)
{
    const float* x    = (const float*)d_in[0];
    const float* rbf  = (const float*)d_in[1];
    const int*   ei   = (const int*)  d_in[2];
    const float* dist = (const float*)d_in[3];
    int k = 4;
    while (k < n_in && in_sizes[k] != 768) k++;
    const float* w_rbf = (const float*)d_in[k];
    const float* sel_w = (const float*)d_in[k + 1];
    const float* w1    = (const float*)d_in[k + 2];
    const float* b1    = (const float*)d_in[k + 3];
    const float* w2    = (const float*)d_in[k + 4];
    const float* b2    = (const float*)d_in[k + 5];
    const float* w3    = (const float*)d_in[k + 6];
    const float* b3    = (const float*)d_in[k + 7];
    const float* wout  = (const float*)d_in[k + 8];

    int E = in_sizes[0] / H;
    int N = out_size / H;

    cudaFuncSetAttribute(k_edge, cudaFuncAttributeMaxDynamicSharedMemorySize, EDGE_SMEM_BYTES);
    cudaFuncSetAttribute(k_mlp,  cudaFuncAttributeMaxDynamicSharedMemorySize, MLP_SMEM_BYTES);

    // fast zero of accumulator + bucket counters via capturable memset nodes
    void* accumPtr = nullptr;
    void* cntPtr = nullptr;
    cudaGetSymbolAddress(&accumPtr, g_accum4);
    cudaGetSymbolAddress(&cntPtr, g_cnt);
    cudaMemsetAsync(accumPtr, 0, (size_t)N * H * sizeof(float));
    cudaMemsetAsync(cntPtr, 0, 16 * sizeof(int));

    k_scatter<<<1024, 256>>>(dist, E);
    k_wprep<<<12, 256>>>(sel_w, w1, w2, w3, wout);

    int maxG = (E + G_TILES * 128 - 1) / (G_TILES * 128);
    k_edge<<<NBUCKETS * maxG, THREADS_E, EDGE_SMEM_BYTES>>>(x, rbf, ei, w_rbf, maxG);
    k_mlp<<<(N + 127) / 128, THREADS_M, MLP_SMEM_BYTES>>>(b1, b2, b3, (float*)d_out, N);
}

// round 15
// speedup vs baseline: 1.0486x; 1.0118x over previous
#include <cuda_runtime.h>
#include <cuda_bf16.h>
#include <cuda_fp16.h>
#include <cstdint>

#define H 128
#define NBUCKETS 9
#define THREADS_E 512
#define THREADS_M 256
#define G_TILES 8
#define CAP 1000000      // per-bucket capacity in g_permB

#define RSTRIDE_E 136    // elems; 272B rows, 17*16B -> ldmatrix conflict-free
#define RSTRIDE_B 272
#define SD_STRIDE 132

// ---------------- device scratch ----------------
__device__ float4 g_accum4[100000 * (H / 4)];   // zeroed by cudaMemsetAsync each launch
__device__ int    g_permB[NBUCKETS * CAP];      // per-bucket edge lists
__device__ int    g_cnt[16];                    // per-bucket counts (memset each launch)
// slots 0..7 experts (fp16, B^T[n][k]=W[k][n]); 8..11 = MLP w1,w2,w3,wout (fp16 hi/lo)
__device__ __align__(16) unsigned short g_wsp_hi[12][128][RSTRIDE_E];
__device__ __align__(16) unsigned short g_wsp_lo[12][128][RSTRIDE_E];

// ---------------- helpers ----------------
__device__ __forceinline__ int bucket_of(float d) {
    float t = (d - 0.8f) / 5.0001f * 8.0f;
    float f = floorf(t);
    return (f >= 0.0f && f < 8.0f) ? (int)f : 8;
}

__device__ __forceinline__ void red_add_v4(float* p, float a, float b, float c, float d) {
    asm volatile("red.global.add.v4.f32 [%0], {%1,%2,%3,%4};"
                 :: "l"(p), "f"(a), "f"(b), "f"(c), "f"(d) : "memory");
}

__device__ __forceinline__ uint32_t smem_u32(const void* p) {
    uint32_t a;
    asm("{ .reg .u64 t; cvta.to.shared.u64 t, %1; cvt.u32.u64 %0, t; }" : "=r"(a) : "l"(p));
    return a;
}

// L2 evict-first policy for streaming (read-once) data
__device__ __forceinline__ uint64_t mk_evict_first() {
    uint64_t p;
    asm("createpolicy.fractional.L2::evict_first.b64 %0, 1.0;" : "=l"(p));
    return p;
}

#define CP16(dst, src) asm volatile("cp.async.cg.shared.global [%0], [%1], 16;" :: "r"(dst), "l"(src))
#define CP16_EF(dst, src, pol) \
    asm volatile("cp.async.cg.shared.global.L2::cache_hint [%0], [%1], 16, %2;" \
                 :: "r"(dst), "l"(src), "l"(pol))
#define CP8(dst, src)  asm volatile("cp.async.ca.shared.global [%0], [%1], 8;"  :: "r"(dst), "l"(src))
#define CP_COMMIT()    asm volatile("cp.async.commit_group;" ::: "memory")
#define CP_WAIT0()     asm volatile("cp.async.wait_group 0;" ::: "memory")

__device__ __forceinline__ void ldsm_x4(uint32_t& r0, uint32_t& r1, uint32_t& r2, uint32_t& r3,
                                        uint32_t addr) {
    asm volatile("ldmatrix.sync.aligned.m8n8.x4.shared.b16 {%0,%1,%2,%3}, [%4];"
                 : "=r"(r0), "=r"(r1), "=r"(r2), "=r"(r3) : "r"(addr));
}

__device__ __forceinline__ void mma_fp16(float* d, uint32_t a0, uint32_t a1, uint32_t a2,
                                         uint32_t a3, uint32_t b0, uint32_t b1) {
    asm volatile("mma.sync.aligned.m16n8k16.row.col.f32.f16.f16.f32 "
                 "{%0,%1,%2,%3}, {%4,%5,%6,%7}, {%8,%9}, {%0,%1,%2,%3};"
                 : "+f"(d[0]), "+f"(d[1]), "+f"(d[2]), "+f"(d[3])
                 : "r"(a0), "r"(a1), "r"(a2), "r"(a3), "r"(b0), "r"(b1));
}

__device__ __forceinline__ uint32_t pack_half2(float v0, float v1) {
    __half h0 = __float2half_rn(v0), h1 = __float2half_rn(v1);
    return (uint32_t)__half_as_ushort(h0) | ((uint32_t)__half_as_ushort(h1) << 16);
}

// fp16 pass for k_mlp: acc[16][4] += A(16x128 stripe at m0) * B^T(128x128)
__device__ __forceinline__ void mma_stripe_fp(float (*acc)[4], uint32_t aBase, uint32_t bBase,
                                              int lane, int m0) {
    uint32_t aAddr = aBase + (uint32_t)(m0 + (lane & 15)) * RSTRIDE_B
                   + (uint32_t)((lane >> 4) << 4);
    uint32_t bAddr = bBase + (uint32_t)((lane & 7) + ((lane >> 4) << 3)) * RSTRIDE_B
                   + (uint32_t)(((lane >> 3) & 1) << 4);
    #pragma unroll
    for (int k0 = 0; k0 < 8; k0++) {
        uint32_t a0, a1, a2, a3;
        ldsm_x4(a0, a1, a2, a3, aAddr + k0 * 32);
        #pragma unroll
        for (int j2 = 0; j2 < 8; j2++) {
            uint32_t b0, b1, b2, b3;
            ldsm_x4(b0, b1, b2, b3, bAddr + j2 * (16 * RSTRIDE_B) + k0 * 32);
            mma_fp16(acc[j2 * 2],     a0, a1, a2, a3, b0, b1);
            mma_fp16(acc[j2 * 2 + 1], a0, a1, a2, a3, b2, b3);
        }
    }
}

// 32x32 warp tile, fp16: acc[2][4][4] += A(32 rows at m0) * B^T(32 cols at n0)
__device__ __forceinline__ void mma_pass32_fp(float (*acc)[4][4], uint32_t aBase, uint32_t bBase,
                                              int lane, int m0, int n0) {
    uint32_t aAddr = aBase + (uint32_t)(m0 + (lane & 15)) * RSTRIDE_B
                   + (uint32_t)((lane >> 4) << 4);
    uint32_t bAddr = bBase + (uint32_t)(n0 + (lane & 7) + ((lane >> 4) << 3)) * RSTRIDE_B
                   + (uint32_t)(((lane >> 3) & 1) << 4);
    #pragma unroll
    for (int k0 = 0; k0 < 8; k0++) {
        uint32_t a0, a1, a2, a3, c0, c1, c2, c3;
        ldsm_x4(a0, a1, a2, a3, aAddr + k0 * 32);
        ldsm_x4(c0, c1, c2, c3, aAddr + 16 * RSTRIDE_B + k0 * 32);
        #pragma unroll
        for (int j2 = 0; j2 < 2; j2++) {
            uint32_t b0, b1, b2, b3;
            ldsm_x4(b0, b1, b2, b3, bAddr + j2 * (16 * RSTRIDE_B) + k0 * 32);
            mma_fp16(acc[0][j2 * 2],     a0, a1, a2, a3, b0, b1);
            mma_fp16(acc[0][j2 * 2 + 1], a0, a1, a2, a3, b2, b3);
            mma_fp16(acc[1][j2 * 2],     c0, c1, c2, c3, b0, b1);
            mma_fp16(acc[1][j2 * 2 + 1], c0, c1, c2, c3, b2, b3);
        }
    }
}

// ---------------- front-end: direct per-bucket scatter (no hist/scan) ----------------
__global__ void k_scatter(const float* __restrict__ dist, int E) {
    int lane = threadIdx.x & 31;
    unsigned ltmask = (1u << lane) - 1u;
    int i = blockIdx.x * blockDim.x + threadIdx.x;
    int stride = gridDim.x * blockDim.x;
    for (; i < E; i += stride) {
        int s = bucket_of(dist[i]);
        unsigned m = __match_any_sync(0xffffffffu, s);
        int leader = __ffs(m) - 1;
        int base = 0;
        if (lane == leader) base = atomicAdd(&g_cnt[s], __popc(m));
        base = __shfl_sync(0xffffffffu, base, leader);
        g_permB[(size_t)s * CAP + base + __popc(m & ltmask)] = i;
    }
}

__global__ void k_wprep(const float* __restrict__ sel_w, const float* __restrict__ w1,
                        const float* __restrict__ w2, const float* __restrict__ w3,
                        const float* __restrict__ wout) {
    int slot = blockIdx.x;
    const float* src;
    bool tr;
    if (slot < 8) { src = sel_w + (size_t)slot * (H * H); tr = true; }
    else {
        const float* m[4] = {w1, w2, w3, wout};
        src = m[slot - 8]; tr = false;
    }
    for (int idx = threadIdx.x; idx < H * H; idx += blockDim.x) {
        int n = idx >> 7, k = idx & 127;
        float w = tr ? src[k * H + n] : src[n * H + k];
        if (slot < 8) {
            g_wsp_hi[slot][n][k] = __half_as_ushort(__float2half_rn(w));
        } else {   // fp16 split-2 for MLP (2-pass)
            __half hh = __float2half_rn(w);
            __half ll = __float2half_rn(w - __half2float(hh));
            g_wsp_hi[slot][n][k] = __half_as_ushort(hh);
            g_wsp_lo[slot][n][k] = __half_as_ushort(ll);
        }
    }
}

// ---------------- kernel: edge expert GEMM (512t, staged v4 scatter, evict-first x) ----------------
#define SM_META 0
#define SM_WT   32
#define SM_PERM (SM_WT + 3072)
#define SM_NODE (SM_PERM + 4096)
#define SM_RBF  (SM_NODE + 4096)
#define SM_XBUF (SM_RBF + 3072 + 32)
#define SM_AHI  (SM_XBUF + 65536)
#define SM_BHI  (SM_AHI + 34816)
#define SM_DST  (SM_BHI + 34816)
#define EDGE_SMEM_BYTES (SM_DST + 128 * SD_STRIDE * 4)

__device__ __forceinline__ void issue_tile(const float* x, const float* rbf,
                                           const int* pt, uint32_t sbase, int t,
                                           uint64_t pol) {
    #pragma unroll 4
    for (int idx = t; idx < 4096; idx += THREADS_E) {
        int r = idx >> 5, seg = idx & 31;
        const char* src = (const char*)(x + (size_t)pt[r] * H) + seg * 16;
        CP16_EF(sbase + SM_XBUF + r * 512 + seg * 16, src, pol);
    }
    if (t < 384) {
        int r = t / 3, p = t - r * 3;
        const char* src = (const char*)(rbf + (size_t)pt[r] * 6) + p * 8;
        CP8(sbase + SM_RBF + r * 24 + p * 8, src);
    }
}

__global__ void __launch_bounds__(THREADS_E, 1)
k_edge(const float* __restrict__ x, const float* __restrict__ rbf,
       const int* __restrict__ eidx, const float* __restrict__ w_rbf, int maxG)
{
    extern __shared__ char sm[];
    int*   meta  = (int*)(sm + SM_META);
    float* sWT   = (float*)(sm + SM_WT);
    int*   permG = (int*)(sm + SM_PERM);
    int*   nodeG = (int*)(sm + SM_NODE);
    float* sRbf  = (float*)(sm + SM_RBF);
    float* sD    = (float*)(sm + SM_DST);
    uint32_t sbase = smem_u32(sm);
    uint64_t pol = mk_evict_first();

    int t = threadIdx.x, wid = t >> 5, lane = t & 31;

    if (t == 0) {
        int s = blockIdx.x / maxG;
        int grp = blockIdx.x - s * maxG;
        int rowBase = grp * (G_TILES * 128);
        int rem = g_cnt[s] - rowBase;
        if (rem <= 0) meta[0] = -1;
        else {
            if (rem > G_TILES * 128) rem = G_TILES * 128;
            meta[0] = s;
            meta[1] = (rem + 127) >> 7;
            meta[2] = rowBase;
            meta[3] = rem;
        }
    }
    __syncthreads();
    int s = meta[0];
    if (s < 0) return;
    int nTiles = meta[1], rowStart = meta[2], rem = meta[3];
    const int* permSrc = g_permB + (size_t)s * CAP + rowStart;

    for (int idx = t; idx < nTiles * 128; idx += THREADS_E)
        permG[idx] = (idx < rem) ? permSrc[idx] : permSrc[0];
    for (int idx = t; idx < 768; idx += THREADS_E) {
        int q = idx >> 7, c = idx & 127;
        sWT[idx] = w_rbf[c * 6 + q];
    }
    __syncthreads();
    for (int idx = t; idx < nTiles * 128; idx += THREADS_E)
        nodeG[idx] = eidx[permG[idx]];

    if (s < 8) {   // expert weight (fp16), once per group
        const char* srcH = (const char*)&g_wsp_hi[s][0][0];
        for (int i = t * 16; i < 34816; i += THREADS_E * 16)
            CP16(sbase + SM_BHI + i, srcH + i);
    }
    issue_tile(x, rbf, permG, sbase, t, pol);
    CP_COMMIT();
    CP_WAIT0();
    __syncthreads();

    int c0 = lane * 4;
    float4 wq[6];
    #pragma unroll
    for (int q = 0; q < 6; q++) wq[q] = *(float4*)&sWT[q * 128 + c0];

    int mi = wid & 3, nj = wid >> 2;
    int m0 = mi * 32, n0 = nj * 32;
    int m0b = wid * 8;

    for (int i = 0; i < nTiles; i++) {
        int rows_i = min(128, rem - i * 128);
        const int* nodeT = nodeG + i * 128;

        // ---- build A(i): h = (rbf @ w_rbf^T) * x -> fp16 ----
        #pragma unroll 2
        for (int m = 0; m < 8; m++) {
            int r = m0b + m;
            bool act = (r < rows_i);
            const float* xr = (const float*)(sm + SM_XBUF + r * 512);
            float rq0 = sRbf[r * 6 + 0], rq1 = sRbf[r * 6 + 1], rq2 = sRbf[r * 6 + 2];
            float rq3 = sRbf[r * 6 + 3], rq4 = sRbf[r * 6 + 4], rq5 = sRbf[r * 6 + 5];
            float4 g;
            g.x = rq0*wq[0].x + rq1*wq[1].x + rq2*wq[2].x + rq3*wq[3].x + rq4*wq[4].x + rq5*wq[5].x;
            g.y = rq0*wq[0].y + rq1*wq[1].y + rq2*wq[2].y + rq3*wq[3].y + rq4*wq[4].y + rq5*wq[5].y;
            g.z = rq0*wq[0].z + rq1*wq[1].z + rq2*wq[2].z + rq3*wq[3].z + rq4*wq[4].z + rq5*wq[5].z;
            g.w = rq0*wq[0].w + rq1*wq[1].w + rq2*wq[2].w + rq3*wq[3].w + rq4*wq[4].w + rq5*wq[5].w;
            float4 xv = *(const float4*)&xr[c0];
            float h0 = act ? g.x * xv.x : 0.f;
            float h1 = act ? g.y * xv.y : 0.f;
            float h2 = act ? g.z * xv.z : 0.f;
            float h3 = act ? g.w * xv.w : 0.f;
            if (s < 8) {
                uint32_t off = (uint32_t)r * RSTRIDE_B + (uint32_t)c0 * 2;
                *(uint32_t*)(sm + SM_AHI + off)     = pack_half2(h0, h1);
                *(uint32_t*)(sm + SM_AHI + off + 4) = pack_half2(h2, h3);
            } else if (act) {
                red_add_v4((float*)g_accum4 + (size_t)nodeT[r] * H + c0, h0, h1, h2, h3);
            }
        }
        __syncthreads();

        // prefetch next tile while MMA runs
        if (i + 1 < nTiles) issue_tile(x, rbf, permG + (i + 1) * 128, sbase, t, pol);
        CP_COMMIT();

        if (s < 8) {
            float acc[2][4][4];
            #pragma unroll
            for (int mt = 0; mt < 2; mt++)
                #pragma unroll
                for (int j = 0; j < 4; j++)
                    acc[mt][j][0] = acc[mt][j][1] = acc[mt][j][2] = acc[mt][j][3] = 0.f;

            mma_pass32_fp(acc, sbase + SM_AHI, sbase + SM_BHI, lane, m0, n0);

            // stage D (own 32x32 region; no pre-sync)
            int lrBase = m0 + (lane >> 2);
            int cBase = n0 + (lane & 3) * 2;
            #pragma unroll
            for (int mt = 0; mt < 2; mt++) {
                #pragma unroll
                for (int j = 0; j < 4; j++) {
                    int lr = lrBase + mt * 16;
                    int col = cBase + j * 8;
                    *(float2*)&sD[lr * SD_STRIDE + col] =
                        make_float2(acc[mt][j][0], acc[mt][j][1]);
                    *(float2*)&sD[(lr + 8) * SD_STRIDE + col] =
                        make_float2(acc[mt][j][2], acc[mt][j][3]);
                }
            }
            __syncthreads();

            // single-phase red.v4 scatter
            #pragma unroll 4
            for (int idx = t; idx < 4096; idx += THREADS_E) {
                int row = idx >> 5, c4 = (idx & 31) << 2;
                if (row < rows_i) {
                    float4 v = *(float4*)&sD[row * SD_STRIDE + c4];
                    red_add_v4((float*)g_accum4 + (size_t)nodeT[row] * H + c4,
                               v.x, v.y, v.z, v.w);
                }
            }
        }
        CP_WAIT0();
        __syncthreads();
    }
}

// ---------------- kernel: fused node MLP (fp16 2-pass, single W buffer, 2 CTAs/SM) ----------------
#define MSM_BIAS 0
#define MSM_A    1536
#define MSM_W    (MSM_A + 34816)            // hi at +0, lo at +34816
#define MLP_SMEM_BYTES (MSM_W + 69632)      // 105,984 B -> 2 CTAs/SM

__device__ __forceinline__ void issue_weight(int slot, uint32_t sbase, int t) {
    const char* srcH = (const char*)&g_wsp_hi[slot][0][0];
    const char* srcL = (const char*)&g_wsp_lo[slot][0][0];
    uint32_t dst = sbase + MSM_W;
    for (int i = t * 16; i < 34816; i += THREADS_M * 16) {
        CP16(dst + i, srcH + i);
        CP16(dst + 34816 + i, srcL + i);
    }
}

__global__ void __launch_bounds__(THREADS_M, 2)
k_mlp(const float* __restrict__ b1, const float* __restrict__ b2,
      const float* __restrict__ b3, float* __restrict__ out, int N)
{
    extern __shared__ char sm[];
    float* sBias = (float*)(sm + MSM_BIAS);
    uint32_t sbase = smem_u32(sm);
    int t = threadIdx.x, wid = t >> 5, lane = t & 31;
    int nb = blockIdx.x * 128;
    int rows = min(128, N - nb);

    issue_weight(8, sbase, t);
    CP_COMMIT();

    // load accumulator rows -> plain fp16 A tile
    const float* accum = (const float*)g_accum4;
    for (int idx = t; idx < 128 * 32; idx += THREADS_M) {
        int r = idx >> 5, c4 = (idx & 31) * 4;
        float4 v = (r < rows) ? *(const float4*)&accum[(size_t)(nb + r) * H + c4]
                              : make_float4(0.f, 0.f, 0.f, 0.f);
        uint32_t off = (uint32_t)r * RSTRIDE_B + (uint32_t)c4 * 2;
        *(uint32_t*)(sm + MSM_A + off)     = pack_half2(v.x, v.y);
        *(uint32_t*)(sm + MSM_A + off + 4) = pack_half2(v.z, v.w);
    }
    if (t < 128) {
        sBias[t]       = b1[t];
        sBias[t + 128] = b2[t];
        sBias[t + 256] = b3[t];
    }

    int m0 = wid * 16;
    int r0 = m0 + (lane >> 2), r1 = r0 + 8, cb = (lane & 3) * 2;

    for (int l = 0; l < 4; l++) {
        CP_WAIT0();        // weight buffer for layer l ready
        __syncthreads();   // + A writes (initial load or previous epilogue) visible

        float acc[16][4];
        #pragma unroll
        for (int j = 0; j < 16; j++) { acc[j][0] = acc[j][1] = acc[j][2] = acc[j][3] = 0.f; }
        mma_stripe_fp(acc, sbase + MSM_A, sbase + MSM_W,         lane, m0);   // A*Wh
        mma_stripe_fp(acc, sbase + MSM_A, sbase + MSM_W + 34816, lane, m0);   // A*Wl
        __syncthreads();   // all W + A reads done

        if (l < 3) { issue_weight(9 + l, sbase, t); CP_COMMIT(); }  // overlap with epilogue

        if (l < 3) {
            const float* bias = sBias + l * 128;
            #pragma unroll
            for (int j = 0; j < 16; j++) {
                int col = j * 8 + cb;
                float v0 = acc[j][0] + bias[col];
                float v1 = acc[j][1] + bias[col + 1];
                float v2 = acc[j][2] + bias[col];
                float v3 = acc[j][3] + bias[col + 1];
                v0 = v0 / (1.f + __expf(-v0));
                v1 = v1 / (1.f + __expf(-v1));
                v2 = v2 / (1.f + __expf(-v2));
                v3 = v3 / (1.f + __expf(-v3));
                uint32_t off0 = (uint32_t)r0 * RSTRIDE_B + (uint32_t)col * 2;
                uint32_t off1 = (uint32_t)r1 * RSTRIDE_B + (uint32_t)col * 2;
                *(uint32_t*)(sm + MSM_A + off0) = pack_half2(v0, v1);
                *(uint32_t*)(sm + MSM_A + off1) = pack_half2(v2, v3);
            }
        } else {
            #pragma unroll
            for (int j = 0; j < 16; j++) {
                int col = j * 8 + cb;
                if (r0 < rows)
                    *(float2*)&out[(size_t)(nb + r0) * H + col] = make_float2(acc[j][0], acc[j][1]);
                if (r1 < rows)
                    *(float2*)&out[(size_t)(nb + r1) * H + col] = make_float2(acc[j][2], acc[j][3]);
            }
        }
    }
}

// ---------------- launcher ----------------
extern "C" void kernel_launch(void* const* d_in, const int* in_sizes, int n_in,
                              void* d_out, int out_size)
{
    const float* x    = (const float*)d_in[0];
    const float* rbf  = (const float*)d_in[1];
    const int*   ei   = (const int*)  d_in[2];
    const float* dist = (const float*)d_in[3];
    int k = 4;
    while (k < n_in && in_sizes[k] != 768) k++;
    const float* w_rbf = (const float*)d_in[k];
    const float* sel_w = (const float*)d_in[k + 1];
    const float* w1    = (const float*)d_in[k + 2];
    const float* b1    = (const float*)d_in[k + 3];
    const float* w2    = (const float*)d_in[k + 4];
    const float* b2    = (const float*)d_in[k + 5];
    const float* w3    = (const float*)d_in[k + 6];
    const float* b3    = (const float*)d_in[k + 7];
    const float* wout  = (const float*)d_in[k + 8];

    int E = in_sizes[0] / H;
    int N = out_size / H;

    cudaFuncSetAttribute(k_edge, cudaFuncAttributeMaxDynamicSharedMemorySize, EDGE_SMEM_BYTES);
    cudaFuncSetAttribute(k_mlp,  cudaFuncAttributeMaxDynamicSharedMemorySize, MLP_SMEM_BYTES);

    // fast zero of accumulator + bucket counters via capturable memset nodes
    void* accumPtr = nullptr;
    void* cntPtr = nullptr;
    cudaGetSymbolAddress(&accumPtr, g_accum4);
    cudaGetSymbolAddress(&cntPtr, g_cnt);
    cudaMemsetAsync(accumPtr, 0, (size_t)N * H * sizeof(float));
    cudaMemsetAsync(cntPtr, 0, 16 * sizeof(int));

    k_scatter<<<1024, 256>>>(dist, E);
    k_wprep<<<12, 256>>>(sel_w, w1, w2, w3, wout);

    int maxG = (E + G_TILES * 128 - 1) / (G_TILES * 128);
    k_edge<<<NBUCKETS * maxG, THREADS_E, EDGE_SMEM_BYTES>>>(x, rbf, ei, w_rbf, maxG);
    k_mlp<<<(N + 127) / 128, THREADS_M, MLP_SMEM_BYTES>>>(b1, b2, b3, (float*)d_out, N);
}